// round 5
// baseline (speedup 1.0000x reference)
#include <cuda_runtime.h>
#include <math.h>
#include <math_constants.h>
#include <cstdint>

// ---------------- problem constants ----------------
#define BATCH      4
#define SEQ        512
#define HID        1024
#define HS         64
#define ENT_HEADS  2
#define REL_HEADS  24
#define TOT_HEADS  (ENT_HEADS + 2 * REL_HEADS)   // 50
#define N_ENT      (ENT_HEADS * 2 * HS)          // 256
#define N_REL      (REL_HEADS * 2 * HS)          // 3072
#define N_TOT      (N_ENT + 2 * N_REL)           // 6400
#define TOKENS     (BATCH * SEQ)                 // 2048
#define MAX_LEN    1024
#define BH         (BATCH * TOT_HEADS)           // 200

// quantization scales
#define S_X   24.0f
#define S_W   1024.0f
#define S_Q   24.0f
#define INV_PROJ (1.0f / (S_X * S_W))
#define INV_LOG  (1.0f / (S_Q * S_Q))

// ---------------- device scratch ----------------
__device__ int8_t g_x8[TOKENS * HID];
__device__ int8_t g_wt8[N_TOT * HID];     // transposed weights [n][k], int8
__device__ int8_t g_q8[BH * SEQ * HS];
__device__ int8_t g_k8[BH * SEQ * HS];
__device__ float  g_bias[N_TOT];
__device__ float  g_cos[MAX_LEN * 16];
__device__ float  g_sin[MAX_LEN * 16];

// ---------------- helpers ----------------
__device__ __forceinline__ uint32_t smem_u32(const void* p) {
    uint32_t a;
    asm("{ .reg .u64 t; cvta.to.shared.u64 t, %1; cvt.u32.u64 %0, t; }" : "=r"(a) : "l"(p));
    return a;
}
__device__ __forceinline__ void cp16(uint32_t saddr, const void* g) {
    asm volatile("cp.async.cg.shared.global [%0], [%1], 16;" :: "r"(saddr), "l"(g) : "memory");
}
#define CP_COMMIT() asm volatile("cp.async.commit_group;" ::: "memory")

__device__ __forceinline__ void ldsm_x4(uint32_t* r, uint32_t addr) {
    asm volatile("ldmatrix.sync.aligned.m8n8.x4.shared.b16 {%0,%1,%2,%3}, [%4];"
        : "=r"(r[0]), "=r"(r[1]), "=r"(r[2]), "=r"(r[3]) : "r"(addr));
}
__device__ __forceinline__ void mma_i8(int* c, const uint32_t* a, const uint32_t* b) {
    asm volatile(
        "mma.sync.aligned.m16n8k32.row.col.s32.s8.s8.s32 "
        "{%0,%1,%2,%3}, {%4,%5,%6,%7}, {%8,%9}, {%0,%1,%2,%3};"
        : "+r"(c[0]), "+r"(c[1]), "+r"(c[2]), "+r"(c[3])
        : "r"(a[0]), "r"(a[1]), "r"(a[2]), "r"(a[3]), "r"(b[0]), "r"(b[1]));
}
__device__ __forceinline__ int q8i(float v, float s) {
    int t = __float2int_rn(v * s);
    return max(-127, min(127, t));
}

// ---------------- kernel 0: rope tables ----------------
__global__ void rope_table_kernel() {
    int t = blockIdx.x * blockDim.x + threadIdx.x;
    if (t >= MAX_LEN * 16) return;
    int pos = t >> 4;
    int a   = t & 15;
    float div = expf((float)(2 * a) * (-logf(10000.0f) / 32.0f));
    float ang = (float)pos * div;
    g_cos[t] = cosf(ang);
    g_sin[t] = sinf(ang);
}

// ---------------- kernel 1: X -> int8 ----------------
__global__ __launch_bounds__(256)
void convert_x_kernel(const float* __restrict__ X) {
    int i = blockIdx.x * 256 + threadIdx.x;      // float4 units
    if (i >= TOKENS * HID / 4) return;
    float4 v = ((const float4*)X)[i];
    ((char4*)g_x8)[i] = make_char4(
        (char)q8i(v.x, S_X), (char)q8i(v.y, S_X),
        (char)q8i(v.z, S_X), (char)q8i(v.w, S_X));
}

// ---------------- kernel 2: W[k][n] -> Wt int8 [n][k] ----------------
__global__ __launch_bounds__(256)
void convert_w_kernel(const float* __restrict__ W, int N, int coloff) {
    __shared__ float t[32][33];
    int n0 = blockIdx.x * 32;
    int k0 = blockIdx.y * 32;
    int tx = threadIdx.x, ty = threadIdx.y;   // block (32, 8)
#pragma unroll
    for (int i = 0; i < 4; ++i)
        t[ty + i * 8][tx] = W[(size_t)(k0 + ty + i * 8) * N + n0 + tx];
    __syncthreads();
#pragma unroll
    for (int i = 0; i < 4; ++i) {
        int n = n0 + ty + i * 8;
        g_wt8[(size_t)(coloff + n) * HID + k0 + tx] = (int8_t)q8i(t[tx][ty + i * 8], S_W);
    }
}

// ---------------- kernel 2b: concat biases ----------------
__global__ void bias_kernel(const float* __restrict__ b_ent,
                            const float* __restrict__ b_head,
                            const float* __restrict__ b_tail) {
    int i = blockIdx.x * 256 + threadIdx.x;
    if (i >= N_TOT) return;
    float v;
    if (i < N_ENT)               v = b_ent[i];
    else if (i < N_ENT + N_REL)  v = b_head[i - N_ENT];
    else                         v = b_tail[i - N_ENT - N_REL];
    g_bias[i] = v;
}

// ---------------- kernel 3: projection GEMM (int8 IMMA) + bias + RoPE ----------------
// CTA: 128 tokens x 128 cols (= ONE head: 64 q | 64 k). 8 warps 4x2, warp 32x64.
// BK=64 (2 k32 steps), 2-stage cp.async. Stride 80B (conflict-free ldmatrix).
#define PJ_STRIDE 80
#define PJ_BUF    10240
#define PJ_STAGE  20480
#define PJ_SMEM   40960

extern __shared__ __align__(128) char dsm[];

__global__ __launch_bounds__(256)
void proj_mma_kernel(const int* __restrict__ xp, const int* __restrict__ yp) {
    uint32_t sb = smem_u32(dsm);
    int tid = threadIdx.x, wid = tid >> 5, lane = tid & 31;
    int head = blockIdx.x;                        // 0..49 global head index
    int m0 = blockIdx.y * 128;
    int warp_m = (wid & 3) * 32, warp_n = (wid >> 2) * 64;

    const int8_t* Xp = g_x8  + (size_t)m0 * HID;
    const int8_t* Wp = g_wt8 + (size_t)head * 128 * HID;

    int acc[2][8][4];
#pragma unroll
    for (int i = 0; i < 2; ++i)
#pragma unroll
        for (int j = 0; j < 8; ++j)
#pragma unroll
            for (int k = 0; k < 4; ++k) acc[i][j][k] = 0;

    // ldmatrix lane geometry (byte offsets)
    int a_row = (lane & 7) + ((lane >> 3) & 1) * 8;
    int a_kb  = (lane >> 4) * 16;
    int b_row = (lane & 7) + ((lane >> 4) & 1) * 8;
    int b_kb  = ((lane >> 3) & 1) * 16;

#define PJ_ISSUE(stage, c) do {                                               \
    int k0 = (c) * 64;                                                        \
    uint32_t base = sb + (stage) * PJ_STAGE;                                  \
    _Pragma("unroll")                                                         \
    for (int it = 0; it < 2; ++it) {                                          \
        int flat = it * 256 + tid;           /* 512 x 16B per buffer */       \
        int rr = flat >> 2, jj = flat & 3;                                    \
        uint32_t so = (uint32_t)(rr * PJ_STRIDE + jj * 16);                   \
        size_t go = (size_t)rr * HID + k0 + jj * 16;                          \
        cp16(base + so,          Xp + go);                                    \
        cp16(base + PJ_BUF + so, Wp + go);                                    \
    }                                                                         \
    CP_COMMIT();                                                              \
} while (0)

    PJ_ISSUE(0, 0);
    for (int c = 0; c < 16; ++c) {
        int st = c & 1;
        if (c + 1 < 16) {
            PJ_ISSUE(st ^ 1, c + 1);
            asm volatile("cp.async.wait_group 1;" ::: "memory");
        } else {
            asm volatile("cp.async.wait_group 0;" ::: "memory");
        }
        __syncthreads();

        uint32_t bA = sb + st * PJ_STAGE;
#pragma unroll
        for (int ks = 0; ks < 2; ++ks) {          // two k32 steps per BK=64
            uint32_t ah[2][4];
#pragma unroll
            for (int mi = 0; mi < 2; ++mi) {
                uint32_t ao = (uint32_t)((warp_m + mi * 16 + a_row) * PJ_STRIDE + a_kb + ks * 32);
                ldsm_x4(ah[mi], bA + ao);
            }
#pragma unroll
            for (int n2 = 0; n2 < 4; ++n2) {
                uint32_t bh[4];
                uint32_t bo = (uint32_t)((warp_n + n2 * 16 + b_row) * PJ_STRIDE + b_kb + ks * 32);
                ldsm_x4(bh, bA + PJ_BUF + bo);
#pragma unroll
                for (int mi = 0; mi < 2; ++mi)
#pragma unroll
                    for (int t = 0; t < 2; ++t)
                        mma_i8(acc[mi][n2 * 2 + t], ah[mi], bh + 2 * t);
            }
        }
        __syncthreads();
    }

    // ---- epilogue: dequant + bias + 2D RoPE, write int8 q/k ----
    int qk = warp_n >> 6;                       // 0 = q half, 1 = k half
    int8_t* outp = qk ? g_k8 : g_q8;
    int colbase = head * 128 + warp_n;
#pragma unroll
    for (int mi = 0; mi < 2; ++mi) {
#pragma unroll
        for (int h = 0; h < 2; ++h) {
            int row = m0 + warp_m + mi * 16 + (lane >> 2) + h * 8;
            int px = xp[row], py = yp[row];
            int b = row >> 9, s = row & 511;
            size_t obase = ((size_t)(b * TOT_HEADS + head) * SEQ + s) * HS;
#pragma unroll
            for (int ni = 0; ni < 8; ++ni) {
                int d = ni * 8 + 2 * (lane & 3);          // 0..62 even
                float v0 = (float)acc[mi][ni][h * 2 + 0] * INV_PROJ + g_bias[colbase + d];
                float v1 = (float)acc[mi][ni][h * 2 + 1] * INV_PROJ + g_bias[colbase + d + 1];
                int p = (d < 32) ? px : py;
                int a = (d & 31) >> 1;
                float cc = g_cos[p * 16 + a], sn = g_sin[p * 16 + a];
                float o0 = v0 * cc - v1 * sn;
                float o1 = v1 * cc + v0 * sn;
                *(char2*)(outp + obase + d) =
                    make_char2((char)q8i(o0, S_Q), (char)q8i(o1, S_Q));
            }
        }
    }
}

// ---------------- kernel 4: logits = Q @ K^T (int8 IMMA) + mask/tril/scale ----------------
// CTA 128x128, K=64 loaded once. smem: Q | K each 128x80B = 10240B.
#define LG_STRIDE 80
#define LG_BUF    10240
#define LG_SMEM   20480

__global__ __launch_bounds__(256)
void logits_mma_kernel(const int* __restrict__ mask, float* __restrict__ out) {
    uint32_t sb = smem_u32(dsm);
    int tid = threadIdx.x, wid = tid >> 5, lane = tid & 31;
    int bh = blockIdx.z;
    int b = bh / TOT_HEADS, g = bh % TOT_HEADS;
    int m0 = blockIdx.y * 128, n0 = blockIdx.x * 128;
    int warp_m = (wid & 3) * 32, warp_n = (wid >> 2) * 64;

    const int8_t* Qb = g_q8 + (size_t)bh * SEQ * HS;
    const int8_t* Kb = g_k8 + (size_t)bh * SEQ * HS;

#pragma unroll
    for (int it = 0; it < 2; ++it) {
        int flat = it * 256 + tid;            // 512 x 16B per buffer
        int rr = flat >> 2, jj = flat & 3;
        uint32_t so = (uint32_t)(rr * LG_STRIDE + jj * 16);
        cp16(sb + so,          Qb + (size_t)(m0 + rr) * HS + jj * 16);
        cp16(sb + LG_BUF + so, Kb + (size_t)(n0 + rr) * HS + jj * 16);
    }
    CP_COMMIT();
    asm volatile("cp.async.wait_group 0;" ::: "memory");
    __syncthreads();

    int acc[2][8][4];
#pragma unroll
    for (int i = 0; i < 2; ++i)
#pragma unroll
        for (int j = 0; j < 8; ++j)
#pragma unroll
            for (int k = 0; k < 4; ++k) acc[i][j][k] = 0;

    int a_row = (lane & 7) + ((lane >> 3) & 1) * 8;
    int a_kb  = (lane >> 4) * 16;
    int b_row = (lane & 7) + ((lane >> 4) & 1) * 8;
    int b_kb  = ((lane >> 3) & 1) * 16;

#pragma unroll
    for (int ks = 0; ks < 2; ++ks) {
        uint32_t ah[2][4];
#pragma unroll
        for (int mi = 0; mi < 2; ++mi) {
            uint32_t ao = (uint32_t)((warp_m + mi * 16 + a_row) * LG_STRIDE + a_kb + ks * 32);
            ldsm_x4(ah[mi], sb + ao);
        }
#pragma unroll
        for (int n2 = 0; n2 < 4; ++n2) {
            uint32_t bhf[4];
            uint32_t bo = (uint32_t)((warp_n + n2 * 16 + b_row) * LG_STRIDE + b_kb + ks * 32);
            ldsm_x4(bhf, sb + LG_BUF + bo);
#pragma unroll
            for (int mi = 0; mi < 2; ++mi)
#pragma unroll
                for (int t = 0; t < 2; ++t)
                    mma_i8(acc[mi][n2 * 2 + t], ah[mi], bhf + 2 * t);
        }
    }

    const int* mrow = mask + b * SEQ;
    bool is_ent = (g < ENT_HEADS);
#pragma unroll
    for (int mi = 0; mi < 2; ++mi) {
#pragma unroll
        for (int h = 0; h < 2; ++h) {
            int m = m0 + warp_m + mi * 16 + (lane >> 2) + h * 8;
            bool pm = (mrow[m] > 0);
            float* orow = out + ((size_t)bh * SEQ + m) * SEQ;
#pragma unroll
            for (int ni = 0; ni < 8; ++ni) {
                int n = n0 + warp_n + ni * 8 + 2 * (lane & 3);
                float v0 = (float)acc[mi][ni][h * 2 + 0] * INV_LOG;
                float v1 = (float)acc[mi][ni][h * 2 + 1] * INV_LOG;
                if (!(pm && mrow[n] > 0))     v0 = -CUDART_INF_F;
                if (!(pm && mrow[n + 1] > 0)) v1 = -CUDART_INF_F;
                if (is_ent) {
                    if (m > n)     v0 -= 1e12f;
                    if (m > n + 1) v1 -= 1e12f;
                }
                *(float2*)(orow + n) = make_float2(v0 * 0.125f, v1 * 0.125f);
            }
        }
    }
}

// ---------------- launch ----------------
extern "C" void kernel_launch(void* const* d_in, const int* in_sizes, int n_in,
                              void* d_out, int out_size) {
    const float* x      = (const float*)d_in[0];
    const int*   mask   = (const int*)  d_in[1];
    const int*   xp     = (const int*)  d_in[2];
    const int*   yp     = (const int*)  d_in[3];
    const float* W_ent  = (const float*)d_in[4];
    const float* b_ent  = (const float*)d_in[5];
    const float* W_head = (const float*)d_in[6];
    const float* b_head = (const float*)d_in[7];
    const float* W_tail = (const float*)d_in[8];
    const float* b_tail = (const float*)d_in[9];
    float* out = (float*)d_out;

    rope_table_kernel<<<(MAX_LEN * 16 + 255) / 256, 256>>>();
    convert_x_kernel<<<(TOKENS * HID / 4 + 255) / 256, 256>>>(x);

    dim3 tb(32, 8);
    convert_w_kernel<<<dim3(N_ENT / 32, HID / 32), tb>>>(W_ent,  N_ENT, 0);
    convert_w_kernel<<<dim3(N_REL / 32, HID / 32), tb>>>(W_head, N_REL, N_ENT);
    convert_w_kernel<<<dim3(N_REL / 32, HID / 32), tb>>>(W_tail, N_REL, N_ENT + N_REL);
    bias_kernel<<<(N_TOT + 255) / 256, 256>>>(b_ent, b_head, b_tail);

    proj_mma_kernel<<<dim3(TOT_HEADS, TOKENS / 128), 256, PJ_SMEM>>>(xp, yp);

    logits_mma_kernel<<<dim3(SEQ / 128, SEQ / 128, BH), 256, LG_SMEM>>>(mask, out);
}

// round 6
// speedup vs baseline: 1.5580x; 1.5580x over previous
#include <cuda_runtime.h>
#include <cuda_bf16.h>
#include <math.h>
#include <math_constants.h>
#include <cstdint>

// ---------------- problem constants ----------------
#define BATCH      4
#define SEQ        512
#define HID        1024
#define HS         64
#define ENT_HEADS  2
#define REL_HEADS  24
#define TOT_HEADS  (ENT_HEADS + 2 * REL_HEADS)   // 50
#define N_ENT      (ENT_HEADS * 2 * HS)          // 256
#define N_REL      (REL_HEADS * 2 * HS)          // 3072
#define N_TOT      (N_ENT + 2 * N_REL)           // 6400
#define TOKENS     (BATCH * SEQ)                 // 2048
#define MAX_LEN    1024
#define BH         (BATCH * TOT_HEADS)           // 200

// ---------------- device scratch ----------------
__device__ __nv_bfloat16 g_x[TOKENS * HID];
__device__ __nv_bfloat16 g_wt[N_TOT * HID];      // transposed weights [n][k]
__device__ __nv_bfloat16 g_q[BH * SEQ * HS];
__device__ __nv_bfloat16 g_k[BH * SEQ * HS];
__device__ float g_bias[N_TOT];
__device__ float g_cos[MAX_LEN * 16];
__device__ float g_sin[MAX_LEN * 16];

// ---------------- ptx helpers (sm_80+ only: no tcgen05) ----------------
__device__ __forceinline__ uint32_t smem_u32(const void* p) {
    uint32_t a;
    asm("{ .reg .u64 t; cvta.to.shared.u64 t, %1; cvt.u32.u64 %0, t; }" : "=r"(a) : "l"(p));
    return a;
}
__device__ __forceinline__ void cp16(uint32_t saddr, const void* g) {
    asm volatile("cp.async.cg.shared.global [%0], [%1], 16;" :: "r"(saddr), "l"(g) : "memory");
}
#define CP_COMMIT() asm volatile("cp.async.commit_group;" ::: "memory")

__device__ __forceinline__ void ldsm_x4(uint32_t* r, uint32_t addr) {
    asm volatile("ldmatrix.sync.aligned.m8n8.x4.shared.b16 {%0,%1,%2,%3}, [%4];"
        : "=r"(r[0]), "=r"(r[1]), "=r"(r[2]), "=r"(r[3]) : "r"(addr));
}
__device__ __forceinline__ void mma16816(float* c, const uint32_t* a, const uint32_t* b) {
    asm volatile(
        "mma.sync.aligned.m16n8k16.row.col.f32.bf16.bf16.f32 "
        "{%0,%1,%2,%3}, {%4,%5,%6,%7}, {%8,%9}, {%0,%1,%2,%3};"
        : "+f"(c[0]), "+f"(c[1]), "+f"(c[2]), "+f"(c[3])
        : "r"(a[0]), "r"(a[1]), "r"(a[2]), "r"(a[3]), "r"(b[0]), "r"(b[1]));
}

// ---------------- kernel 0: rope tables ----------------
__global__ void rope_table_kernel() {
    int t = blockIdx.x * blockDim.x + threadIdx.x;
    if (t >= MAX_LEN * 16) return;
    int pos = t >> 4;
    int a   = t & 15;
    float div = expf((float)(2 * a) * (-logf(10000.0f) / 32.0f));
    float ang = (float)pos * div;
    g_cos[t] = cosf(ang);
    g_sin[t] = sinf(ang);
}

// ---------------- kernel 1: X -> bf16 ----------------
__global__ __launch_bounds__(256)
void convert_x_kernel(const float* __restrict__ X) {
    int i = blockIdx.x * 256 + threadIdx.x;
    if (i >= TOKENS * HID / 2) return;
    float2 v = ((const float2*)X)[i];
    ((__nv_bfloat162*)g_x)[i] =
        __halves2bfloat162(__float2bfloat16(v.x), __float2bfloat16(v.y));
}

// ---------------- kernel 2: W[k][n] -> Wt bf16 [n][k] ----------------
__global__ __launch_bounds__(256)
void convert_w_kernel(const float* __restrict__ W, int N, int coloff) {
    __shared__ float t[32][33];
    int n0 = blockIdx.x * 32;
    int k0 = blockIdx.y * 32;
    int tx = threadIdx.x, ty = threadIdx.y;   // block (32, 8)
#pragma unroll
    for (int i = 0; i < 4; ++i)
        t[ty + i * 8][tx] = W[(size_t)(k0 + ty + i * 8) * N + n0 + tx];
    __syncthreads();
#pragma unroll
    for (int i = 0; i < 4; ++i) {
        int n = n0 + ty + i * 8;
        g_wt[(size_t)(coloff + n) * HID + k0 + tx] = __float2bfloat16(t[tx][ty + i * 8]);
    }
}

// ---------------- kernel 2b: concat biases ----------------
__global__ void bias_kernel(const float* __restrict__ b_ent,
                            const float* __restrict__ b_head,
                            const float* __restrict__ b_tail) {
    int i = blockIdx.x * 256 + threadIdx.x;
    if (i >= N_TOT) return;
    float v;
    if (i < N_ENT)               v = b_ent[i];
    else if (i < N_ENT + N_REL)  v = b_head[i - N_ENT];
    else                         v = b_tail[i - N_ENT - N_REL];
    g_bias[i] = v;
}

// ---------------- kernel 3: projection GEMM (bf16 HMMA) + bias + RoPE ----------------
// CTA: 256 tokens x 128 cols (ONE head: 64 q | 64 k). 8 warps 4x2, warp 64x64.
// BK=64, 3-stage cp.async. Per stage: A 256x72 bf16 (36864B) + B 128x72 (18432B).
#define PJ_STRIDE 72
#define PJ_ABUF   36864
#define PJ_STAGE  55296
#define PJ_SMEM   165888

extern __shared__ __align__(128) char dsm[];

__global__ __launch_bounds__(256)
void proj_mma_kernel(const int* __restrict__ xp, const int* __restrict__ yp) {
    uint32_t sb = smem_u32(dsm);
    int tid = threadIdx.x, wid = tid >> 5, lane = tid & 31;
    int head = blockIdx.x;                      // 0..49 global head index
    int m0 = blockIdx.y * 256;
    int warp_m = (wid & 3) * 64, warp_n = (wid >> 2) * 64;

    const __nv_bfloat16* Xp = g_x  + (size_t)m0 * HID;
    const __nv_bfloat16* Wp = g_wt + (size_t)head * 128 * HID;

    float acc[4][8][4];
#pragma unroll
    for (int i = 0; i < 4; ++i)
#pragma unroll
        for (int j = 0; j < 8; ++j)
#pragma unroll
            for (int k = 0; k < 4; ++k) acc[i][j][k] = 0.0f;

    int a_row = (lane & 7) + ((lane >> 3) & 1) * 8;
    int a_col = (lane >> 4) * 8;
    int b_row = (lane & 7) + ((lane >> 4) & 1) * 8;
    int b_col = ((lane >> 3) & 1) * 8;

#define PJ_ISSUE(stage, c) do {                                               \
    int k0 = (c) * 64;                                                        \
    uint32_t base = sb + (stage) * PJ_STAGE;                                  \
    _Pragma("unroll")                                                         \
    for (int it = 0; it < 8; ++it) {         /* A: 2048 16B units */          \
        int flat = it * 256 + tid;                                            \
        int rr = flat >> 3, jj = flat & 7;                                    \
        cp16(base + (uint32_t)(rr * 144 + jj * 16),                           \
             Xp + (size_t)rr * HID + k0 + jj * 8);                            \
    }                                                                         \
    _Pragma("unroll")                                                         \
    for (int it = 0; it < 4; ++it) {         /* B: 1024 16B units */          \
        int flat = it * 256 + tid;                                            \
        int rr = flat >> 3, jj = flat & 7;                                    \
        cp16(base + PJ_ABUF + (uint32_t)(rr * 144 + jj * 16),                 \
             Wp + (size_t)rr * HID + k0 + jj * 8);                            \
    }                                                                         \
    CP_COMMIT();                                                              \
} while (0)

    PJ_ISSUE(0, 0);
    PJ_ISSUE(1, 1);
    for (int c = 0; c < 16; ++c) {
        asm volatile("cp.async.wait_group 1;" ::: "memory");
        __syncthreads();
        if (c + 2 < 16) PJ_ISSUE((c + 2) % 3, c + 2);

        uint32_t bA = sb + (c % 3) * PJ_STAGE;
#pragma unroll
        for (int k16 = 0; k16 < 64; k16 += 16) {
            uint32_t ah[4][4];
#pragma unroll
            for (int mi = 0; mi < 4; ++mi) {
                uint32_t ao = (uint32_t)((warp_m + mi * 16 + a_row) * PJ_STRIDE + a_col + k16) * 2;
                ldsm_x4(ah[mi], bA + ao);
            }
#pragma unroll
            for (int n2 = 0; n2 < 4; ++n2) {
                uint32_t bh[4];
                uint32_t bo = (uint32_t)((warp_n + n2 * 16 + b_row) * PJ_STRIDE + b_col + k16) * 2;
                ldsm_x4(bh, bA + PJ_ABUF + bo);
#pragma unroll
                for (int mi = 0; mi < 4; ++mi)
#pragma unroll
                    for (int t = 0; t < 2; ++t)
                        mma16816(acc[mi][n2 * 2 + t], ah[mi], bh + 2 * t);
            }
        }
    }

    // ---- epilogue: bias + 2D RoPE, write bf16 q/k ----
    int qk = warp_n >> 6;                       // 0 = q half, 1 = k half
    __nv_bfloat16* outp = qk ? g_k : g_q;
    int colbase = head * 128 + warp_n;
#pragma unroll
    for (int mi = 0; mi < 4; ++mi) {
#pragma unroll
        for (int h = 0; h < 2; ++h) {
            int row = m0 + warp_m + mi * 16 + (lane >> 2) + h * 8;
            int px = xp[row], py = yp[row];
            int b = row >> 9, s = row & 511;
            size_t obase = ((size_t)(b * TOT_HEADS + head) * SEQ + s) * HS;
#pragma unroll
            for (int ni = 0; ni < 8; ++ni) {
                int d = ni * 8 + 2 * (lane & 3);          // 0..62 even
                float v0 = acc[mi][ni][h * 2 + 0] + g_bias[colbase + d];
                float v1 = acc[mi][ni][h * 2 + 1] + g_bias[colbase + d + 1];
                int p = (d < 32) ? px : py;
                int a = (d & 31) >> 1;
                float cc = g_cos[p * 16 + a], sn = g_sin[p * 16 + a];
                float o0 = v0 * cc - v1 * sn;
                float o1 = v1 * cc + v0 * sn;
                *(__nv_bfloat162*)(outp + obase + d) =
                    __halves2bfloat162(__float2bfloat16(o0), __float2bfloat16(o1));
            }
        }
    }
}

// ---------------- kernel 4: logits = Q @ K^T (bf16 HMMA) + mask/tril/scale ----------------
// CTA 128x128, K=64 loaded once. smem: Q | K each 128x72 bf16 = 18432B.
#define LG_STRIDE 72
#define LG_BUF    18432
#define LG_SMEM   36864

__global__ __launch_bounds__(256)
void logits_mma_kernel(const int* __restrict__ mask, float* __restrict__ out) {
    uint32_t sb = smem_u32(dsm);
    int tid = threadIdx.x, wid = tid >> 5, lane = tid & 31;
    int bh = blockIdx.z;
    int b = bh / TOT_HEADS, g = bh % TOT_HEADS;
    int m0 = blockIdx.y * 128, n0 = blockIdx.x * 128;
    int warp_m = (wid & 3) * 32, warp_n = (wid >> 2) * 64;

    const __nv_bfloat16* Qb = g_q + (size_t)bh * SEQ * HS;
    const __nv_bfloat16* Kb = g_k + (size_t)bh * SEQ * HS;

#pragma unroll
    for (int it = 0; it < 4; ++it) {
        int flat = it * 256 + tid;            // 1024 16B units per buffer
        int r = flat >> 3, j = flat & 7;
        uint32_t so = (uint32_t)(r * LG_STRIDE + j * 8) * 2;
        cp16(sb + so,          Qb + (size_t)(m0 + r) * HS + j * 8);
        cp16(sb + LG_BUF + so, Kb + (size_t)(n0 + r) * HS + j * 8);
    }
    CP_COMMIT();
    asm volatile("cp.async.wait_group 0;" ::: "memory");
    __syncthreads();

    float acc[2][8][4];
#pragma unroll
    for (int i = 0; i < 2; ++i)
#pragma unroll
        for (int j = 0; j < 8; ++j)
#pragma unroll
            for (int k = 0; k < 4; ++k) acc[i][j][k] = 0.0f;

    int a_row = (lane & 7) + ((lane >> 3) & 1) * 8;
    int a_col = (lane >> 4) * 8;
    int b_row = (lane & 7) + ((lane >> 4) & 1) * 8;
    int b_col = ((lane >> 3) & 1) * 8;

#pragma unroll
    for (int k16 = 0; k16 < 64; k16 += 16) {
        uint32_t ah[2][4];
#pragma unroll
        for (int mi = 0; mi < 2; ++mi) {
            uint32_t ao = (uint32_t)((warp_m + mi * 16 + a_row) * LG_STRIDE + a_col + k16) * 2;
            ldsm_x4(ah[mi], sb + ao);
        }
#pragma unroll
        for (int n2 = 0; n2 < 4; ++n2) {
            uint32_t bhf[4];
            uint32_t bo = (uint32_t)((warp_n + n2 * 16 + b_row) * LG_STRIDE + b_col + k16) * 2;
            ldsm_x4(bhf, sb + LG_BUF + bo);
#pragma unroll
            for (int mi = 0; mi < 2; ++mi)
#pragma unroll
                for (int t = 0; t < 2; ++t)
                    mma16816(acc[mi][n2 * 2 + t], ah[mi], bhf + 2 * t);
        }
    }

    const int* mrow = mask + b * SEQ;
    bool is_ent = (g < ENT_HEADS);
#pragma unroll
    for (int mi = 0; mi < 2; ++mi) {
#pragma unroll
        for (int h = 0; h < 2; ++h) {
            int m = m0 + warp_m + mi * 16 + (lane >> 2) + h * 8;
            bool pm = (mrow[m] > 0);
            float* orow = out + ((size_t)bh * SEQ + m) * SEQ;
#pragma unroll
            for (int ni = 0; ni < 8; ++ni) {
                int n = n0 + warp_n + ni * 8 + 2 * (lane & 3);
                float v0 = acc[mi][ni][h * 2 + 0];
                float v1 = acc[mi][ni][h * 2 + 1];
                if (!(pm && mrow[n] > 0))     v0 = -CUDART_INF_F;
                if (!(pm && mrow[n + 1] > 0)) v1 = -CUDART_INF_F;
                if (is_ent) {
                    if (m > n)     v0 -= 1e12f;
                    if (m > n + 1) v1 -= 1e12f;
                }
                __stcs(reinterpret_cast<float2*>(orow + n),
                       make_float2(v0 * 0.125f, v1 * 0.125f));
            }
        }
    }
}

// ---------------- launch ----------------
extern "C" void kernel_launch(void* const* d_in, const int* in_sizes, int n_in,
                              void* d_out, int out_size) {
    const float* x      = (const float*)d_in[0];
    const int*   mask   = (const int*)  d_in[1];
    const int*   xp     = (const int*)  d_in[2];
    const int*   yp     = (const int*)  d_in[3];
    const float* W_ent  = (const float*)d_in[4];
    const float* b_ent  = (const float*)d_in[5];
    const float* W_head = (const float*)d_in[6];
    const float* b_head = (const float*)d_in[7];
    const float* W_tail = (const float*)d_in[8];
    const float* b_tail = (const float*)d_in[9];
    float* out = (float*)d_out;

    cudaFuncSetAttribute(proj_mma_kernel,   cudaFuncAttributeMaxDynamicSharedMemorySize, PJ_SMEM);
    cudaFuncSetAttribute(logits_mma_kernel, cudaFuncAttributeMaxDynamicSharedMemorySize, LG_SMEM);

    rope_table_kernel<<<(MAX_LEN * 16 + 255) / 256, 256>>>();
    convert_x_kernel<<<(TOKENS * HID / 2 + 255) / 256, 256>>>(x);

    dim3 tb(32, 8);
    convert_w_kernel<<<dim3(N_ENT / 32, HID / 32), tb>>>(W_ent,  N_ENT, 0);
    convert_w_kernel<<<dim3(N_REL / 32, HID / 32), tb>>>(W_head, N_REL, N_ENT);
    convert_w_kernel<<<dim3(N_REL / 32, HID / 32), tb>>>(W_tail, N_REL, N_ENT + N_REL);
    bias_kernel<<<(N_TOT + 255) / 256, 256>>>(b_ent, b_head, b_tail);

    proj_mma_kernel<<<dim3(TOT_HEADS, TOKENS / 256), 256, PJ_SMEM>>>(xp, yp);

    logits_mma_kernel<<<dim3(SEQ / 128, SEQ / 128, BH), 256, LG_SMEM>>>(mask, out);
}

// round 7
// speedup vs baseline: 1.6593x; 1.0650x over previous
#include <cuda_runtime.h>
#include <cuda_bf16.h>
#include <math.h>
#include <math_constants.h>
#include <cstdint>

// ---------------- problem constants ----------------
#define BATCH      4
#define SEQ        512
#define HID        1024
#define HS         64
#define ENT_HEADS  2
#define REL_HEADS  24
#define TOT_HEADS  (ENT_HEADS + 2 * REL_HEADS)   // 50
#define N_ENT      (ENT_HEADS * 2 * HS)          // 256
#define N_REL      (REL_HEADS * 2 * HS)          // 3072
#define N_TOT      (N_ENT + 2 * N_REL)           // 6400
#define TOKENS     (BATCH * SEQ)                 // 2048
#define MAX_LEN    1024
#define BH         (BATCH * TOT_HEADS)           // 200

// prep kernel grid partition
#define PREP_W_BLOCKS   ((N_TOT / 32) * (HID / 32))          // 6400
#define PREP_X_BLOCKS   (TOKENS * HID / 4 / 256)             // 2048
#define PREP_R_BLOCKS   (MAX_LEN * 16 / 256)                 // 64
#define PREP_B_BLOCKS   ((N_TOT + 255) / 256)                // 25
#define PREP_GRID       (PREP_W_BLOCKS + PREP_X_BLOCKS + PREP_R_BLOCKS + PREP_B_BLOCKS)

// ---------------- device scratch ----------------
__device__ __nv_bfloat16 g_x[TOKENS * HID];
__device__ __nv_bfloat16 g_wt[N_TOT * HID];      // transposed weights [n][k]
__device__ __nv_bfloat16 g_q[BH * SEQ * HS];
__device__ __nv_bfloat16 g_k[BH * SEQ * HS];
__device__ float g_bias[N_TOT];
__device__ float g_cos[MAX_LEN * 16];
__device__ float g_sin[MAX_LEN * 16];

// ---------------- ptx helpers (sm_80+ only: no tcgen05) ----------------
__device__ __forceinline__ uint32_t smem_u32(const void* p) {
    uint32_t a;
    asm("{ .reg .u64 t; cvta.to.shared.u64 t, %1; cvt.u32.u64 %0, t; }" : "=r"(a) : "l"(p));
    return a;
}
__device__ __forceinline__ void cp16(uint32_t saddr, const void* g) {
    asm volatile("cp.async.cg.shared.global [%0], [%1], 16;" :: "r"(saddr), "l"(g) : "memory");
}
#define CP_COMMIT() asm volatile("cp.async.commit_group;" ::: "memory")

__device__ __forceinline__ void ldsm_x4(uint32_t* r, uint32_t addr) {
    asm volatile("ldmatrix.sync.aligned.m8n8.x4.shared.b16 {%0,%1,%2,%3}, [%4];"
        : "=r"(r[0]), "=r"(r[1]), "=r"(r[2]), "=r"(r[3]) : "r"(addr));
}
__device__ __forceinline__ void mma16816(float* c, const uint32_t* a, const uint32_t* b) {
    asm volatile(
        "mma.sync.aligned.m16n8k16.row.col.f32.bf16.bf16.f32 "
        "{%0,%1,%2,%3}, {%4,%5,%6,%7}, {%8,%9}, {%0,%1,%2,%3};"
        : "+f"(c[0]), "+f"(c[1]), "+f"(c[2]), "+f"(c[3])
        : "r"(a[0]), "r"(a[1]), "r"(a[2]), "r"(a[3]), "r"(b[0]), "r"(b[1]));
}

// ---------------- kernel 1: fused prep (rope tables + x->bf16 + W transpose + bias) ----
__global__ __launch_bounds__(256)
void prep_kernel(const float* __restrict__ X,
                 const float* __restrict__ W_ent, const float* __restrict__ W_head,
                 const float* __restrict__ W_tail,
                 const float* __restrict__ b_ent, const float* __restrict__ b_head,
                 const float* __restrict__ b_tail) {
    __shared__ float t[32][33];
    int bid = blockIdx.x;
    int tid = threadIdx.x;

    if (bid < PREP_W_BLOCKS) {
        // -------- W transpose + bf16 convert --------
        int nblk = bid / (HID / 32);
        int kblk = bid % (HID / 32);
        int gn0 = nblk * 32;          // global col in [0, 6400)
        int k0  = kblk * 32;
        const float* W; int N; int loc;
        if (gn0 < N_ENT)                { W = W_ent;  N = N_ENT; loc = gn0; }
        else if (gn0 < N_ENT + N_REL)   { W = W_head; N = N_REL; loc = gn0 - N_ENT; }
        else                            { W = W_tail; N = N_REL; loc = gn0 - N_ENT - N_REL; }
        int tx = tid & 31, ty = tid >> 5;  // 32 x 8
#pragma unroll
        for (int i = 0; i < 4; ++i)
            t[ty + i * 8][tx] = W[(size_t)(k0 + ty + i * 8) * N + loc + tx];
        __syncthreads();
#pragma unroll
        for (int i = 0; i < 4; ++i)
            g_wt[(size_t)(gn0 + ty + i * 8) * HID + k0 + tx] =
                __float2bfloat16(t[tx][ty + i * 8]);
        return;
    }
    bid -= PREP_W_BLOCKS;

    if (bid < PREP_X_BLOCKS) {
        // -------- X -> bf16 (float4 granularity) --------
        int i = bid * 256 + tid;                  // float4 units
        float4 v = ((const float4*)X)[i];
        ((__nv_bfloat162*)g_x)[i * 2]     = __halves2bfloat162(__float2bfloat16(v.x), __float2bfloat16(v.y));
        ((__nv_bfloat162*)g_x)[i * 2 + 1] = __halves2bfloat162(__float2bfloat16(v.z), __float2bfloat16(v.w));
        return;
    }
    bid -= PREP_X_BLOCKS;

    if (bid < PREP_R_BLOCKS) {
        // -------- rope tables --------
        int tt = bid * 256 + tid;
        int pos = tt >> 4;
        int a   = tt & 15;
        float div = expf((float)(2 * a) * (-logf(10000.0f) / 32.0f));
        float ang = (float)pos * div;
        g_cos[tt] = cosf(ang);
        g_sin[tt] = sinf(ang);
        return;
    }
    bid -= PREP_R_BLOCKS;

    // -------- bias concat --------
    {
        int i = bid * 256 + tid;
        if (i >= N_TOT) return;
        float v;
        if (i < N_ENT)               v = b_ent[i];
        else if (i < N_ENT + N_REL)  v = b_head[i - N_ENT];
        else                         v = b_tail[i - N_ENT - N_REL];
        g_bias[i] = v;
    }
}

// ---------------- kernel 2: projection GEMM (bf16 HMMA) + bias + RoPE ----------------
// CTA: 256 tokens x 128 cols (ONE head: 64 q | 64 k). 8 warps 4x2, warp 64x64.
// BK=64, 3-stage cp.async. Per stage: A 256x72 bf16 (36864B) + B 128x72 (18432B).
#define PJ_STRIDE 72
#define PJ_ABUF   36864
#define PJ_STAGE  55296
#define PJ_SMEM   165888

extern __shared__ __align__(128) char dsm[];

__global__ __launch_bounds__(256)
void proj_mma_kernel(const int* __restrict__ xp, const int* __restrict__ yp) {
    uint32_t sb = smem_u32(dsm);
    int tid = threadIdx.x, wid = tid >> 5, lane = tid & 31;
    int head = blockIdx.x;                      // 0..49 global head index
    int m0 = blockIdx.y * 256;
    int warp_m = (wid & 3) * 64, warp_n = (wid >> 2) * 64;

    const __nv_bfloat16* Xp = g_x  + (size_t)m0 * HID;
    const __nv_bfloat16* Wp = g_wt + (size_t)head * 128 * HID;

    float acc[4][8][4];
#pragma unroll
    for (int i = 0; i < 4; ++i)
#pragma unroll
        for (int j = 0; j < 8; ++j)
#pragma unroll
            for (int k = 0; k < 4; ++k) acc[i][j][k] = 0.0f;

    int a_row = (lane & 7) + ((lane >> 3) & 1) * 8;
    int a_col = (lane >> 4) * 8;
    int b_row = (lane & 7) + ((lane >> 4) & 1) * 8;
    int b_col = ((lane >> 3) & 1) * 8;

#define PJ_ISSUE(stage, c) do {                                               \
    int k0 = (c) * 64;                                                        \
    uint32_t base = sb + (stage) * PJ_STAGE;                                  \
    _Pragma("unroll")                                                         \
    for (int it = 0; it < 8; ++it) {         /* A: 2048 16B units */          \
        int flat = it * 256 + tid;                                            \
        int rr = flat >> 3, jj = flat & 7;                                    \
        cp16(base + (uint32_t)(rr * 144 + jj * 16),                           \
             Xp + (size_t)rr * HID + k0 + jj * 8);                            \
    }                                                                         \
    _Pragma("unroll")                                                         \
    for (int it = 0; it < 4; ++it) {         /* B: 1024 16B units */          \
        int flat = it * 256 + tid;                                            \
        int rr = flat >> 3, jj = flat & 7;                                    \
        cp16(base + PJ_ABUF + (uint32_t)(rr * 144 + jj * 16),                 \
             Wp + (size_t)rr * HID + k0 + jj * 8);                            \
    }                                                                         \
    CP_COMMIT();                                                              \
} while (0)

    PJ_ISSUE(0, 0);
    PJ_ISSUE(1, 1);
    for (int c = 0; c < 16; ++c) {
        asm volatile("cp.async.wait_group 1;" ::: "memory");
        __syncthreads();
        if (c + 2 < 16) PJ_ISSUE((c + 2) % 3, c + 2);

        uint32_t bA = sb + (c % 3) * PJ_STAGE;
#pragma unroll
        for (int k16 = 0; k16 < 64; k16 += 16) {
            uint32_t ah[4][4];
#pragma unroll
            for (int mi = 0; mi < 4; ++mi) {
                uint32_t ao = (uint32_t)((warp_m + mi * 16 + a_row) * PJ_STRIDE + a_col + k16) * 2;
                ldsm_x4(ah[mi], bA + ao);
            }
#pragma unroll
            for (int n2 = 0; n2 < 4; ++n2) {
                uint32_t bh[4];
                uint32_t bo = (uint32_t)((warp_n + n2 * 16 + b_row) * PJ_STRIDE + b_col + k16) * 2;
                ldsm_x4(bh, bA + PJ_ABUF + bo);
#pragma unroll
                for (int mi = 0; mi < 4; ++mi)
#pragma unroll
                    for (int t = 0; t < 2; ++t)
                        mma16816(acc[mi][n2 * 2 + t], ah[mi], bh + 2 * t);
            }
        }
    }

    // ---- epilogue: bias + 2D RoPE, write bf16 q/k ----
    int qk = warp_n >> 6;                       // 0 = q half, 1 = k half
    __nv_bfloat16* outp = qk ? g_k : g_q;
    int colbase = head * 128 + warp_n;
#pragma unroll
    for (int mi = 0; mi < 4; ++mi) {
#pragma unroll
        for (int h = 0; h < 2; ++h) {
            int row = m0 + warp_m + mi * 16 + (lane >> 2) + h * 8;
            int px = xp[row], py = yp[row];
            int b = row >> 9, s = row & 511;
            size_t obase = ((size_t)(b * TOT_HEADS + head) * SEQ + s) * HS;
#pragma unroll
            for (int ni = 0; ni < 8; ++ni) {
                int d = ni * 8 + 2 * (lane & 3);          // 0..62 even
                float v0 = acc[mi][ni][h * 2 + 0] + g_bias[colbase + d];
                float v1 = acc[mi][ni][h * 2 + 1] + g_bias[colbase + d + 1];
                int p = (d < 32) ? px : py;
                int a = (d & 31) >> 1;
                float cc = g_cos[p * 16 + a], sn = g_sin[p * 16 + a];
                float o0 = v0 * cc - v1 * sn;
                float o1 = v1 * cc + v0 * sn;
                *(__nv_bfloat162*)(outp + obase + d) =
                    __halves2bfloat162(__float2bfloat16(o0), __float2bfloat16(o1));
            }
        }
    }
}

// ---------------- kernel 3: logits = Q @ K^T (bf16 HMMA) + mask/tril/scale ----------------
// CTA 128x128, K=64 loaded once. smem: Q | K each 128x72 bf16 = 18432B.
#define LG_STRIDE 72
#define LG_BUF    18432
#define LG_SMEM   36864

__global__ __launch_bounds__(256)
void logits_mma_kernel(const int* __restrict__ mask, float* __restrict__ out) {
    uint32_t sb = smem_u32(dsm);
    int tid = threadIdx.x, wid = tid >> 5, lane = tid & 31;
    int bh = blockIdx.z;
    int b = bh / TOT_HEADS, g = bh % TOT_HEADS;
    int m0 = blockIdx.y * 128, n0 = blockIdx.x * 128;
    int warp_m = (wid & 3) * 32, warp_n = (wid >> 2) * 64;

    const __nv_bfloat16* Qb = g_q + (size_t)bh * SEQ * HS;
    const __nv_bfloat16* Kb = g_k + (size_t)bh * SEQ * HS;

#pragma unroll
    for (int it = 0; it < 4; ++it) {
        int flat = it * 256 + tid;            // 1024 16B units per buffer
        int r = flat >> 3, j = flat & 7;
        uint32_t so = (uint32_t)(r * LG_STRIDE + j * 8) * 2;
        cp16(sb + so,          Qb + (size_t)(m0 + r) * HS + j * 8);
        cp16(sb + LG_BUF + so, Kb + (size_t)(n0 + r) * HS + j * 8);
    }
    CP_COMMIT();
    asm volatile("cp.async.wait_group 0;" ::: "memory");
    __syncthreads();

    float acc[2][8][4];
#pragma unroll
    for (int i = 0; i < 2; ++i)
#pragma unroll
        for (int j = 0; j < 8; ++j)
#pragma unroll
            for (int k = 0; k < 4; ++k) acc[i][j][k] = 0.0f;

    int a_row = (lane & 7) + ((lane >> 3) & 1) * 8;
    int a_col = (lane >> 4) * 8;
    int b_row = (lane & 7) + ((lane >> 4) & 1) * 8;
    int b_col = ((lane >> 3) & 1) * 8;

#pragma unroll
    for (int k16 = 0; k16 < 64; k16 += 16) {
        uint32_t ah[2][4];
#pragma unroll
        for (int mi = 0; mi < 2; ++mi) {
            uint32_t ao = (uint32_t)((warp_m + mi * 16 + a_row) * LG_STRIDE + a_col + k16) * 2;
            ldsm_x4(ah[mi], sb + ao);
        }
#pragma unroll
        for (int n2 = 0; n2 < 4; ++n2) {
            uint32_t bhf[4];
            uint32_t bo = (uint32_t)((warp_n + n2 * 16 + b_row) * LG_STRIDE + b_col + k16) * 2;
            ldsm_x4(bhf, sb + LG_BUF + bo);
#pragma unroll
            for (int mi = 0; mi < 2; ++mi)
#pragma unroll
                for (int t = 0; t < 2; ++t)
                    mma16816(acc[mi][n2 * 2 + t], ah[mi], bhf + 2 * t);
        }
    }

    const int* mrow = mask + b * SEQ;
    bool is_ent = (g < ENT_HEADS);
#pragma unroll
    for (int mi = 0; mi < 2; ++mi) {
#pragma unroll
        for (int h = 0; h < 2; ++h) {
            int m = m0 + warp_m + mi * 16 + (lane >> 2) + h * 8;
            bool pm = (mrow[m] > 0);
            float* orow = out + ((size_t)bh * SEQ + m) * SEQ;
#pragma unroll
            for (int ni = 0; ni < 8; ++ni) {
                int n = n0 + warp_n + ni * 8 + 2 * (lane & 3);
                float v0 = acc[mi][ni][h * 2 + 0];
                float v1 = acc[mi][ni][h * 2 + 1];
                if (!(pm && mrow[n] > 0))     v0 = -CUDART_INF_F;
                if (!(pm && mrow[n + 1] > 0)) v1 = -CUDART_INF_F;
                if (is_ent) {
                    if (m > n)     v0 -= 1e12f;
                    if (m > n + 1) v1 -= 1e12f;
                }
                __stcs(reinterpret_cast<float2*>(orow + n),
                       make_float2(v0 * 0.125f, v1 * 0.125f));
            }
        }
    }
}

// ---------------- launch ----------------
extern "C" void kernel_launch(void* const* d_in, const int* in_sizes, int n_in,
                              void* d_out, int out_size) {
    const float* x      = (const float*)d_in[0];
    const int*   mask   = (const int*)  d_in[1];
    const int*   xp     = (const int*)  d_in[2];
    const int*   yp     = (const int*)  d_in[3];
    const float* W_ent  = (const float*)d_in[4];
    const float* b_ent  = (const float*)d_in[5];
    const float* W_head = (const float*)d_in[6];
    const float* b_head = (const float*)d_in[7];
    const float* W_tail = (const float*)d_in[8];
    const float* b_tail = (const float*)d_in[9];
    float* out = (float*)d_out;

    cudaFuncSetAttribute(proj_mma_kernel,   cudaFuncAttributeMaxDynamicSharedMemorySize, PJ_SMEM);
    cudaFuncSetAttribute(logits_mma_kernel, cudaFuncAttributeMaxDynamicSharedMemorySize, LG_SMEM);

    prep_kernel<<<PREP_GRID, 256>>>(x, W_ent, W_head, W_tail, b_ent, b_head, b_tail);

    proj_mma_kernel<<<dim3(TOT_HEADS, TOKENS / 256), 256, PJ_SMEM>>>(xp, yp);

    logits_mma_kernel<<<dim3(SEQ / 128, SEQ / 128, BH), 256, LG_SMEM>>>(mask, out);
}